// round 4
// baseline (speedup 1.0000x reference)
#include <cuda_runtime.h>
#include <cuda_fp16.h>
#include <cstdint>
#include <cstddef>

#define NNODES 55296
#define NEDGES 221184
#define N32 (NNODES * 32)

// ------------------------- device scratch (no allocs) -----------------------
__device__ __align__(256) float g_h[2 * N32];                       // hidden [b][n][32]
__device__ __align__(256) float g_agg[2 * N32];                     // scatter acc
__device__ __align__(256) unsigned long long g_t2[(size_t)NEDGES * 32]; // (t,t) pairs
__device__ __align__(256) float g_ew2p[32 * 1024];                  // ew2 [k][o][h]
__device__ __align__(256) __half g_We[(size_t)NEDGES * 1024];       // [e][o][h] fp16

// ------------------------- f32x2 helpers ------------------------------------
__device__ __forceinline__ unsigned long long pack2(float x, float y) {
    unsigned long long r;
    asm("mov.b64 %0, {%1, %2};" : "=l"(r) : "f"(x), "f"(y));
    return r;
}
__device__ __forceinline__ float2 unpack2(unsigned long long v) {
    float2 r;
    asm("mov.b64 {%0, %1}, %2;" : "=f"(r.x), "=f"(r.y) : "l"(v));
    return r;
}
__device__ __forceinline__ void fma2(unsigned long long& d, unsigned long long a,
                                     unsigned long long b) {
    asm("fma.rn.f32x2 %0, %1, %2, %0;" : "+l"(d) : "l"(a), "l"(b));
}
__device__ __forceinline__ unsigned long long add2(unsigned long long a,
                                                   unsigned long long b) {
    unsigned long long r;
    asm("add.rn.f32x2 %0, %1, %2;" : "=l"(r) : "l"(a), "l"(b));
    return r;
}
__device__ __forceinline__ float fsig(float x) { return 1.f / (1.f + __expf(-x)); }

// ------------------------- k0: zero the accumulator --------------------------
__global__ void zero_kernel() {
    int i = blockIdx.x * 256 + threadIdx.x;
    if (i < 2 * N32) g_agg[i] = 0.f;
}

// ------------------------- k1: reorder ew2 [k][h*32+o] -> [k][o*32+h] --------
__global__ void reorder_kernel(const float* __restrict__ ew2) {
    int i = blockIdx.x * 256 + threadIdx.x;
    if (i < 32768) {
        int k = i >> 10, r = i & 1023, o = r >> 5, h = r & 31;
        g_ew2p[i] = ew2[(k << 10) + h * 32 + o];
    }
}

// ------------------------- k2: t = relu(rel@ew1+eb1), stored duplicated ------
__global__ void t_kernel(const float4* __restrict__ rel4,
                         const float* __restrict__ ew1,
                         const float* __restrict__ eb1) {
    int g = blockIdx.x * 256 + threadIdx.x;
    int e = g >> 5, k = g & 31;
    if (e >= NEDGES) return;
    float4 r = rel4[e];
    float v = eb1[k] + r.x * ew1[k] + r.y * ew1[32 + k] + r.z * ew1[64 + k] +
              r.w * ew1[96 + k];
    v = fmaxf(v, 0.f);
    g_t2[(size_t)e * 32 + k] = pack2(v, v);
}

// ------------------------- k3: h0 projection (warp per node) -----------------
__global__ __launch_bounds__(256) void h0_kernel(const float* __restrict__ x,
                                                 const float* __restrict__ pw1,
                                                 const float* __restrict__ pb1,
                                                 const float* __restrict__ pw2,
                                                 const float* __restrict__ pb2) {
    __shared__ float sW1[1024], sW2[1024];
    int tid = threadIdx.x, lane = tid & 31;
    for (int i = tid; i < 1024; i += 256) { sW1[i] = pw1[i]; sW2[i] = pw2[i]; }
    __syncthreads();
    int gw = blockIdx.x * 8 + (tid >> 5);  // 0 .. 2*NNODES-1
    float xr = x[(size_t)gw * 32 + lane];
    float t1 = pb1[lane];
#pragma unroll
    for (int h = 0; h < 32; h++)
        t1 = fmaf(__shfl_sync(0xffffffffu, xr, h), sW1[h * 32 + lane], t1);
    t1 = fmaxf(t1, 0.f);
    float o = pb2[lane];
#pragma unroll
    for (int h = 0; h < 32; h++)
        o = fmaf(__shfl_sync(0xffffffffu, t1, h), sW2[h * 32 + lane], o);
    g_h[(size_t)gw * 32 + lane] = o;
}

// ------------------------- k4: We = t @ ew2 + eb2 -> fp16 [e][o][h] ----------
// 512 thr: o = tid>>4, hp = tid&15 (covers h=2hp,2hp+1). 128 edges/block.
__global__ __launch_bounds__(512, 1) void We_kernel(const float* __restrict__ eb2) {
    const int tid = threadIdx.x;
    const int o = tid >> 4, hp = tid & 15;
    unsigned long long w2[32];
#pragma unroll
    for (int k = 0; k < 32; k++)
        w2[k] = *(const unsigned long long*)&g_ew2p[k * 1024 + o * 32 + 2 * hp];
    const unsigned long long ebp =
        pack2(eb2[(2 * hp) * 32 + o], eb2[(2 * hp + 1) * 32 + o]);

    __shared__ __align__(16) unsigned long long sT[256];  // 8 edges x 32 pairs
    const int ebase = blockIdx.x * 128;
    for (int g = 0; g < 16; g++) {
        int e0 = ebase + g * 8;
        __syncthreads();
        ((float*)sT)[tid] = ((const float*)g_t2)[(size_t)e0 * 64 + tid];
        __syncthreads();
#pragma unroll 2
        for (int ee = 0; ee < 8; ee++) {
            const ulonglong2* tp = (const ulonglong2*)(sT + ee * 32);
            unsigned long long a0 = ebp, a1 = 0;
#pragma unroll
            for (int q = 0; q < 16; q++) {
                ulonglong2 tq = tp[q];
                fma2(a0, tq.x, w2[2 * q]);
                fma2(a1, tq.y, w2[2 * q + 1]);
            }
            float2 s = unpack2(add2(a0, a1));
            ((__half2*)g_We)[(size_t)(e0 + ee) * 512 + tid] =
                __floats2half2_rn(s.x, s.y);
        }
    }
}

// ------------------------- k5: msg + scatter (warp per edge, lane = o) -------
__global__ __launch_bounds__(256) void msg_kernel(const int* __restrict__ src,
                                                  const int* __restrict__ dst) {
    __shared__ __align__(16) float ns[8][2][32];
    const int w = threadIdx.x >> 5, lane = threadIdx.x & 31;
    const int e = blockIdx.x * 8 + w;
    int s = __ldg(&src[e]);
    int d = __ldg(&dst[e]);
    ns[w][0][lane] = g_h[(size_t)s * 32 + lane];
    ns[w][1][lane] = g_h[N32 + (size_t)s * 32 + lane];
    __syncwarp();
    const uint4* wp = (const uint4*)(g_We + (size_t)e * 1024 + lane * 32);
    uint4 q0 = wp[0], q1 = wp[1], q2 = wp[2], q3 = wp[3];
    uint32_t rr[16] = {q0.x, q0.y, q0.z, q0.w, q1.x, q1.y, q1.z, q1.w,
                       q2.x, q2.y, q2.z, q2.w, q3.x, q3.y, q3.z, q3.w};
    float a0 = 0.f, a1 = 0.f;
#pragma unroll
    for (int j = 0; j < 16; j++) {
        float2 wf = __half22float2(*(__half2*)&rr[j]);
        float2 p0 = *(const float2*)&ns[w][0][2 * j];
        float2 p1 = *(const float2*)&ns[w][1][2 * j];
        a0 += p0.x * wf.x + p0.y * wf.y;
        a1 += p1.x * wf.x + p1.y * wf.y;
    }
    atomicAdd(&g_agg[(size_t)d * 32 + lane], a0);
    atomicAdd(&g_agg[N32 + (size_t)d * 32 + lane], a1);
}

// ------------------------- k6: relu + GRU cell (warp per (b,n)) --------------
__global__ __launch_bounds__(256) void gru_kernel(const float* __restrict__ convb,
                                                  const float* __restrict__ wih,
                                                  const float* __restrict__ whh,
                                                  const float* __restrict__ bih,
                                                  const float* __restrict__ bhh,
                                                  float* __restrict__ outp) {
    __shared__ float sWih[3072], sWhh[3072];  // transposed: [h][j], j=0..95
    int tid = threadIdx.x, lane = tid & 31;
    for (int i = tid; i < 3072; i += 256) {
        int j = i >> 5, h = i & 31;
        sWih[h * 96 + j] = wih[i];
        sWhh[h * 96 + j] = whh[i];
    }
    __syncthreads();
    int gw = blockIdx.x * 8 + (tid >> 5);  // (b,n) flat
    size_t idx = (size_t)gw * 32 + lane;
    float node = fmaxf(g_agg[idx] + convb[lane], 0.f);
    float hid = g_h[idx];
    float gx0 = bih[lane], gx1 = bih[32 + lane], gx2 = bih[64 + lane];
    float gh0 = bhh[lane], gh1 = bhh[32 + lane], gh2 = bhh[64 + lane];
#pragma unroll
    for (int h = 0; h < 32; h++) {
        float nv = __shfl_sync(0xffffffffu, node, h);
        float hv = __shfl_sync(0xffffffffu, hid, h);
        const float* wi = &sWih[h * 96];
        const float* wh = &sWhh[h * 96];
        gx0 = fmaf(nv, wi[lane], gx0);
        gx1 = fmaf(nv, wi[32 + lane], gx1);
        gx2 = fmaf(nv, wi[64 + lane], gx2);
        gh0 = fmaf(hv, wh[lane], gh0);
        gh1 = fmaf(hv, wh[32 + lane], gh1);
        gh2 = fmaf(hv, wh[64 + lane], gh2);
    }
    float r = fsig(gx0 + gh0);
    float z = fsig(gx1 + gh1);
    float n = tanhf(gx2 + r * gh2);
    float hn = (1.f - z) * n + z * hid;
    g_h[idx] = hn;
    if (outp) outp[idx] = hn;
}

// ------------------------- launch -------------------------------------------
extern "C" void kernel_launch(void* const* d_in, const int* in_sizes, int n_in,
                              void* d_out, int out_size) {
    const float* x     = (const float*)d_in[0];
    const float* rel   = (const float*)d_in[1];
    const float* pw1   = (const float*)d_in[2];
    const float* pb1   = (const float*)d_in[3];
    const float* pw2   = (const float*)d_in[4];
    const float* pb2   = (const float*)d_in[5];
    const float* ew1   = (const float*)d_in[6];
    const float* eb1   = (const float*)d_in[7];
    const float* ew2   = (const float*)d_in[8];
    const float* eb2   = (const float*)d_in[9];
    const float* convb = (const float*)d_in[10];
    const float* wih   = (const float*)d_in[11];
    const float* whh   = (const float*)d_in[12];
    const float* bih   = (const float*)d_in[13];
    const float* bhh   = (const float*)d_in[14];
    const int*   src   = (const int*)d_in[15];
    const int*   dst   = (const int*)d_in[16];
    float* out = (float*)d_out;

    reorder_kernel<<<128, 256>>>(ew2);
    t_kernel<<<(NEDGES * 32) / 256, 256>>>((const float4*)rel, ew1, eb1);
    h0_kernel<<<(2 * NNODES) / 8, 256>>>(x, pw1, pb1, pw2, pb2);
    We_kernel<<<NEDGES / 128, 512>>>(eb2);
    for (int step = 0; step < 3; step++) {
        zero_kernel<<<(2 * N32 + 255) / 256, 256>>>();
        msg_kernel<<<NEDGES / 8, 256>>>(src, dst);
        gru_kernel<<<(2 * NNODES) / 8, 256>>>(convb, wih, whh, bih, bhh,
                                              step == 2 ? out : nullptr);
    }
}